// round 2
// baseline (speedup 1.0000x reference)
#include <cuda_runtime.h>
#include <cstdint>

// Problem constants
#define N_ATOMS 20000
#define N_EDGES 640000
#define NB      128    // n_atom_basis == n_filters
#define N_RBF   20

// -------- device scratch (no allocations allowed) --------
__device__ float g_h[N_ATOMS * NB];    // x @ W_in2f
__device__ float g_agg[N_ATOMS * NB];  // segment sum accumulator
__device__ float g_t[N_ATOMS * NB];    // ssp(agg@Wout1+b) intermediate

__device__ __forceinline__ float sspf(float x) {
    // softplus(x) - ln(2), computed stably: max(x,0) + log1p(exp(-|x|)) - ln2
    return fmaxf(x, 0.0f) + log1pf(expf(-fabsf(x))) - 0.69314718055994531f;
}

// -------- zero the accumulator --------
__global__ void zero_kernel(float4* __restrict__ p, int n4) {
    int i = blockIdx.x * blockDim.x + threadIdx.x;
    if (i < n4) p[i] = make_float4(0.f, 0.f, 0.f, 0.f);
}

// -------- generic [rows,128] @ [128,128] (+bias)(+ssp) --------
// 128 threads/block, 8 rows per block. Input row tile in smem; W streamed
// from global (L1-resident after first block on each SM).
template <bool DOSSP, bool DOBIAS>
__global__ __launch_bounds__(128) void gemm128_kernel(
    const float* __restrict__ A, const float* __restrict__ W,
    const float* __restrict__ bias, float* __restrict__ C, int nrows)
{
    __shared__ float xs[8 * NB];
    const int row0 = blockIdx.x * 8;
    const int tid  = threadIdx.x;

    for (int i = tid; i < 8 * NB; i += 128) {
        int r = row0 + (i >> 7);
        xs[i] = (r < nrows) ? A[row0 * NB + i] : 0.0f;
    }
    __syncthreads();

    const int c = tid;
    float acc[8];
#pragma unroll
    for (int r = 0; r < 8; r++) acc[r] = DOBIAS ? bias[c] : 0.0f;

#pragma unroll 4
    for (int k = 0; k < NB; k++) {
        float w = W[k * NB + c];
#pragma unroll
        for (int r = 0; r < 8; r++) acc[r] += xs[r * NB + k] * w;
    }

#pragma unroll
    for (int r = 0; r < 8; r++) {
        int row = row0 + r;
        if (row < nrows) {
            float v = acc[r];
            if (DOSSP) v = sspf(v);
            C[row * NB + c] = v;
        }
    }
}

// -------- fused edge kernel --------
// Persistent blocks (1/SM). Per 64-edge tile:
//   phi = ssp(f_ij @ W1 + b1)      -> smem [64][128]
//   wij = phi @ W2 (reg-blocked)   -> registers (8 edges x 4 cols / thread)
//   epilogue: (+b2) * rcut * h[idx_j], atomicAdd into agg[idx_i]
#define BE 64
#define EDGE_THREADS 256
// smem layout (floats)
#define SM_W1  0                    // 20*128 = 2560
#define SM_B1  2560                 // 128
#define SM_W2  2688                 // 128*128 = 16384
#define SM_B2  19072                // 128
#define SM_FS  19200                // 64*20 = 1280
#define SM_PHI 20480                // 64*128 = 8192
#define SM_TOTAL_FLOATS 28672       // 114688 bytes

__global__ __launch_bounds__(EDGE_THREADS, 1) void edge_kernel(
    const float* __restrict__ f_ij, const float* __restrict__ rcut,
    const int* __restrict__ idx_i, const int* __restrict__ idx_j,
    const float* __restrict__ W1, const float* __restrict__ b1,
    const float* __restrict__ W2, const float* __restrict__ b2)
{
    extern __shared__ float sm[];
    float* W1s  = sm + SM_W1;
    float* b1s  = sm + SM_B1;
    float* W2s  = sm + SM_W2;
    float* b2s  = sm + SM_B2;
    float* fs   = sm + SM_FS;
    float* phis = sm + SM_PHI;

    const int tid = threadIdx.x;

    // Stage weights once per block
    for (int i = tid; i < N_RBF * NB; i += EDGE_THREADS) W1s[i] = W1[i];
    for (int i = tid; i < NB; i += EDGE_THREADS) { b1s[i] = b1[i]; b2s[i] = b2[i]; }
    for (int i = tid; i < NB * NB; i += EDGE_THREADS) W2s[i] = W2[i];
    __syncthreads();

    const int warp = tid >> 5;
    const int lane = tid & 31;
    const int c0   = lane * 4;
    const int ntiles = N_EDGES / BE;   // 10000, exact

    for (int tile = blockIdx.x; tile < ntiles; tile += gridDim.x) {
        const int e0 = tile * BE;

        // Stage f_ij tile
        for (int i = tid; i < BE * N_RBF; i += EDGE_THREADS)
            fs[i] = f_ij[e0 * N_RBF + i];
        __syncthreads();

        // Layer 1 + ssp -> phis[e][k]
        for (int it = 0; it < (BE * NB) / EDGE_THREADS; it++) {   // 32 iters
            int o = it * EDGE_THREADS + tid;
            int e = o >> 7;
            int k = o & 127;
            float a = b1s[k];
#pragma unroll
            for (int r = 0; r < N_RBF; r++)
                a += fs[e * N_RBF + r] * W1s[r * NB + k];
            phis[o] = sspf(a);
        }
        __syncthreads();

        // Layer 2: each warp owns 8 edges; each lane 4 consecutive columns.
        float4 acc[8];
#pragma unroll
        for (int j = 0; j < 8; j++) acc[j] = make_float4(0.f, 0.f, 0.f, 0.f);

        const float* phibase = phis + (warp * 8) * NB;
        for (int k = 0; k < NB; k++) {
            float4 wv = *(const float4*)(W2s + k * NB + c0);
#pragma unroll
            for (int j = 0; j < 8; j++) {
                float a = phibase[j * NB + k];
                acc[j].x += a * wv.x;
                acc[j].y += a * wv.y;
                acc[j].z += a * wv.z;
                acc[j].w += a * wv.w;
            }
        }

        // Epilogue: +b2, *rcut, gather h[idx_j], scatter-add to agg[idx_i]
        const float bx = b2s[c0 + 0], by = b2s[c0 + 1];
        const float bz = b2s[c0 + 2], bw = b2s[c0 + 3];
#pragma unroll
        for (int j = 0; j < 8; j++) {
            int e = e0 + warp * 8 + j;
            float rc = rcut[e];
            int ji = idx_j[e];
            int ii = idx_i[e];
            float4 hv = *(const float4*)(g_h + ji * NB + c0);
            float* dst = g_agg + ii * NB + c0;
            atomicAdd(dst + 0, (acc[j].x + bx) * rc * hv.x);
            atomicAdd(dst + 1, (acc[j].y + by) * rc * hv.y);
            atomicAdd(dst + 2, (acc[j].z + bz) * rc * hv.z);
            atomicAdd(dst + 3, (acc[j].w + bw) * rc * hv.w);
        }
        __syncthreads();   // protect fs/phis before next tile
    }
}

extern "C" void kernel_launch(void* const* d_in, const int* in_sizes, int n_in,
                              void* d_out, int out_size)
{
    const float* x       = (const float*)d_in[0];
    const float* f_ij    = (const float*)d_in[1];
    const float* rcut_ij = (const float*)d_in[2];
    const int*   idx_i   = (const int*)d_in[3];
    const int*   idx_j   = (const int*)d_in[4];
    const float* W_in2f  = (const float*)d_in[5];
    const float* W_filt1 = (const float*)d_in[6];
    const float* b_filt1 = (const float*)d_in[7];
    const float* W_filt2 = (const float*)d_in[8];
    const float* b_filt2 = (const float*)d_in[9];
    const float* W_out1  = (const float*)d_in[10];
    const float* b_out1  = (const float*)d_in[11];
    const float* W_out2  = (const float*)d_in[12];
    const float* b_out2  = (const float*)d_in[13];
    float* out = (float*)d_out;

    void *p_h = nullptr, *p_agg = nullptr, *p_t = nullptr;
    cudaGetSymbolAddress(&p_h, g_h);
    cudaGetSymbolAddress(&p_agg, g_agg);
    cudaGetSymbolAddress(&p_t, g_t);
    float* h   = (float*)p_h;
    float* agg = (float*)p_agg;
    float* t   = (float*)p_t;

    int nsm = 148;
    cudaDeviceGetAttribute(&nsm, cudaDevAttrMultiProcessorCount, 0);

    cudaFuncSetAttribute(edge_kernel,
                         cudaFuncAttributeMaxDynamicSharedMemorySize,
                         SM_TOTAL_FLOATS * sizeof(float));

    // 1) zero the accumulator
    {
        int n4 = (N_ATOMS * NB) / 4;
        int blocks = (n4 + 255) / 256;
        zero_kernel<<<blocks, 256>>>((float4*)agg, n4);
    }
    // 2) h = x @ W_in2f
    gemm128_kernel<false, false><<<(N_ATOMS + 7) / 8, 128>>>(x, W_in2f, nullptr, h, N_ATOMS);
    // 3) fused edge kernel (filter MLP + gather + scatter-add)
    edge_kernel<<<nsm, EDGE_THREADS, SM_TOTAL_FLOATS * sizeof(float)>>>(
        f_ij, rcut_ij, idx_i, idx_j, W_filt1, b_filt1, W_filt2, b_filt2);
    // 4) t = ssp(agg @ W_out1 + b_out1)
    gemm128_kernel<true, true><<<(N_ATOMS + 7) / 8, 128>>>(agg, W_out1, b_out1, t, N_ATOMS);
    // 5) out = t @ W_out2 + b_out2
    gemm128_kernel<false, true><<<(N_ATOMS + 7) / 8, 128>>>(t, W_out2, b_out2, out, N_ATOMS);
}

// round 5
// speedup vs baseline: 2.0676x; 2.0676x over previous
#include <cuda_runtime.h>
#include <cstdint>

// Problem constants
#define N_ATOMS 20000
#define N_EDGES 640000
#define NB      128
#define N_RBF   20

// -------- device scratch --------
__device__ float g_h[N_ATOMS * NB];
__device__ float g_agg[N_ATOMS * NB];
__device__ float g_t[N_ATOMS * NB];

__device__ __forceinline__ float sspf(float x) {
    return fmaxf(x, 0.0f) + log1pf(expf(-fabsf(x))) - 0.69314718055994531f;
}
// cvt.rna.tf32.f32 needs a .b32 destination (ptxas rejects .f32 dst)
__device__ __forceinline__ uint32_t to_tf32_bits(float x) {
    uint32_t r; asm("cvt.rna.tf32.f32 %0, %1;" : "=r"(r) : "f"(x)); return r;
}
__device__ __forceinline__ float to_tf32(float x) {
    return __uint_as_float(to_tf32_bits(x));
}

// m16n8k8 tf32 mma (sm_80+, no arch-specific 'a' features needed)
__device__ __forceinline__ void mma16n8k8(float4& c,
                                          float a0, float a1, float a2, float a3,
                                          float b0, float b1) {
    asm volatile(
        "mma.sync.aligned.m16n8k8.row.col.f32.tf32.tf32.f32 "
        "{%0,%1,%2,%3}, {%4,%5,%6,%7}, {%8,%9}, {%0,%1,%2,%3};"
        : "+f"(c.x), "+f"(c.y), "+f"(c.z), "+f"(c.w)
        : "r"(__float_as_uint(a0)), "r"(__float_as_uint(a1)),
          "r"(__float_as_uint(a2)), "r"(__float_as_uint(a3)),
          "r"(__float_as_uint(b0)), "r"(__float_as_uint(b1)));
}

__device__ __forceinline__ void red_v4(float* p, float a, float b, float c, float d) {
    asm volatile("red.global.add.v4.f32 [%0], {%1, %2, %3, %4};"
                 :: "l"(p), "f"(a), "f"(b), "f"(c), "f"(d) : "memory");
}

// -------- zero kernel --------
__global__ void zero_kernel(float4* __restrict__ p, int n4) {
    int i = blockIdx.x * blockDim.x + threadIdx.x;
    if (i < n4) p[i] = make_float4(0.f, 0.f, 0.f, 0.f);
}

// -------- [rows,128] @ [128,128] (+bias)(+ssp), 16 rows/block --------
template <bool DOSSP, bool DOBIAS>
__global__ __launch_bounds__(128) void gemm128_kernel(
    const float* __restrict__ A, const float* __restrict__ W,
    const float* __restrict__ bias, float* __restrict__ C, int nrows)
{
    __shared__ float xs[16 * NB];
    const int row0 = blockIdx.x * 16;
    const int tid = threadIdx.x;

    for (int i = tid; i < 16 * NB; i += 128) {
        int r = row0 + (i >> 7);
        xs[i] = (r < nrows) ? A[row0 * NB + i] : 0.0f;
    }
    __syncthreads();

    const int c = tid;
    float acc[16];
#pragma unroll
    for (int r = 0; r < 16; r++) acc[r] = DOBIAS ? bias[c] : 0.0f;

#pragma unroll 4
    for (int k = 0; k < NB; k++) {
        float w = W[k * NB + c];
#pragma unroll
        for (int r = 0; r < 16; r++) acc[r] += xs[r * NB + k] * w;
    }
#pragma unroll
    for (int r = 0; r < 16; r++) {
        int row = row0 + r;
        if (row < nrows) {
            float v = acc[r];
            if (DOSSP) v = sspf(v);
            C[row * NB + c] = v;
        }
    }
}

// ======================= fused mma.sync edge kernel =======================
// 256 threads = 8 warps; tile = 128 edges; warp w owns edges [w*16, w*16+16).
// layer1: phi = ssp(f @ W1 + b1)   (mma, K padded 20->24, 3 k-tiles)
// layer2: D  = phi @ W2            (mma, K=128, 16 k-steps, 16 n-tiles)
// epilogue: (D + b2) * rcut * h[idx_j] -> red.v4 into agg[idx_i]
#define ET 256
#define FS_STRIDE 36
#define PHI_STRIDE 132

// smem float offsets
#define OFF_W1P 0        // 3*16*32*2  = 3072   (layer1 B fragment pairs)
#define OFF_W2P 3072     // 16*16*32*2 = 16384  (layer2 B fragment pairs)
#define OFF_B1  19456    // 128
#define OFF_B2  19584    // 128
#define OFF_FS  19712    // 128*36 = 4608
#define OFF_PHI 24320    // 128*132 = 16896
#define SMEM_FLOATS 41216
#define SMEM_BYTES (SMEM_FLOATS * 4)

__global__ __launch_bounds__(ET, 1) void edge_kernel(
    const float* __restrict__ f_ij, const float* __restrict__ rcut,
    const int* __restrict__ idx_i, const int* __restrict__ idx_j,
    const float* __restrict__ W1, const float* __restrict__ b1,
    const float* __restrict__ W2, const float* __restrict__ b2)
{
    extern __shared__ float sm[];
    float* w1p = sm + OFF_W1P;
    float* w2p = sm + OFF_W2P;
    float* b1s = sm + OFF_B1;
    float* b2s = sm + OFF_B2;
    float* fs  = sm + OFF_FS;
    float* phi = sm + OFF_PHI;

    const int tid  = threadIdx.x;
    const int warp = tid >> 5;
    const int lane = tid & 31;
    const int g    = lane >> 2;   // row group 0..7
    const int t    = lane & 3;    // thread-in-group 0..3
    const int m0   = warp * 16;

    // ---- stage W1 into fragment-pair layout (3 k-tiles x 16 n-tiles) ----
    for (int i = tid; i < 3 * 16 * 32; i += ET) {
        int kt = i >> 9, rem = i & 511, nt = rem >> 5, l = rem & 31;
        int gg = l >> 2, tt = l & 3;
        int k = kt * 8 + tt, n = nt * 8 + gg;
        float v0 = (k     < N_RBF) ? W1[k * NB + n]       : 0.0f;
        float v1 = (k + 4 < N_RBF) ? W1[(k + 4) * NB + n] : 0.0f;
        w1p[i * 2 + 0] = to_tf32(v0);
        w1p[i * 2 + 1] = to_tf32(v1);
    }
    // ---- stage W2 into fragment-pair layout (16 x 16 tiles) ----
    for (int i = tid; i < 16 * 16 * 32; i += ET) {
        int ks = i >> 9, rem = i & 511, nt = rem >> 5, l = rem & 31;
        int gg = l >> 2, tt = l & 3;
        int k = ks * 8 + tt, n = nt * 8 + gg;
        w2p[i * 2 + 0] = to_tf32(W2[k * NB + n]);
        w2p[i * 2 + 1] = to_tf32(W2[(k + 4) * NB + n]);
    }
    for (int i = tid; i < NB; i += ET) { b1s[i] = b1[i]; b2s[i] = b2[i]; }
    // zero the padded f columns (20..35) once; never rewritten
    for (int i = tid; i < 128 * (FS_STRIDE - N_RBF); i += ET) {
        int e = i / (FS_STRIDE - N_RBF);
        int k = N_RBF + i % (FS_STRIDE - N_RBF);
        fs[e * FS_STRIDE + k] = 0.0f;
    }
    __syncthreads();

    const int ntiles = N_EDGES / 128;   // 5000 exact

    for (int tile = blockIdx.x; tile < ntiles; tile += gridDim.x) {
        const int e0 = tile * 128;

        // ---- stage f tile (coalesced read, stride-36 smem) ----
        {
            const float* fsrc = f_ij + (size_t)e0 * N_RBF;
            for (int i = tid; i < 128 * N_RBF; i += ET) {
                int e = i / N_RBF, k = i - e * N_RBF;
                fs[e * FS_STRIDE + k] = to_tf32(__ldg(fsrc + i));
            }
        }
        __syncthreads();

        // ---- layer 1: c1 = f @ W1 ----
        float4 c1[16];
#pragma unroll
        for (int nt = 0; nt < 16; nt++) c1[nt] = make_float4(0.f, 0.f, 0.f, 0.f);
#pragma unroll
        for (int kt = 0; kt < 3; kt++) {
            const int kb = kt * 8;
            float a0 = fs[(m0 + g)     * FS_STRIDE + kb + t];
            float a1 = fs[(m0 + g + 8) * FS_STRIDE + kb + t];
            float a2 = fs[(m0 + g)     * FS_STRIDE + kb + t + 4];
            float a3 = fs[(m0 + g + 8) * FS_STRIDE + kb + t + 4];
            const float* bp = w1p + ((kt * 16) * 32 + lane) * 2;
#pragma unroll
            for (int nt = 0; nt < 16; nt++) {
                float2 b = *(const float2*)(bp + nt * 64);
                mma16n8k8(c1[nt], a0, a1, a2, a3, b.x, b.y);
            }
        }

        // ---- ssp + bias -> phi (warp-private rows) ----
#pragma unroll
        for (int nt = 0; nt < 16; nt++) {
            const int n0 = nt * 8 + 2 * t;
            float bb0 = b1s[n0], bb1 = b1s[n0 + 1];
            float2 lo, hi;
            lo.x = to_tf32(sspf(c1[nt].x + bb0));
            lo.y = to_tf32(sspf(c1[nt].y + bb1));
            hi.x = to_tf32(sspf(c1[nt].z + bb0));
            hi.y = to_tf32(sspf(c1[nt].w + bb1));
            *(float2*)(phi + (m0 + g)     * PHI_STRIDE + n0) = lo;
            *(float2*)(phi + (m0 + g + 8) * PHI_STRIDE + n0) = hi;
        }
        __syncwarp();

        // ---- layer 2: c2 = phi @ W2 ----
        float4 c2[16];
#pragma unroll
        for (int nt = 0; nt < 16; nt++) c2[nt] = make_float4(0.f, 0.f, 0.f, 0.f);
        for (int ks = 0; ks < 16; ks++) {
            const int kb = ks * 8;
            float a0 = phi[(m0 + g)     * PHI_STRIDE + kb + t];
            float a1 = phi[(m0 + g + 8) * PHI_STRIDE + kb + t];
            float a2 = phi[(m0 + g)     * PHI_STRIDE + kb + t + 4];
            float a3 = phi[(m0 + g + 8) * PHI_STRIDE + kb + t + 4];
            const float* bp = w2p + ((ks * 16) * 32 + lane) * 2;
#pragma unroll
            for (int nt = 0; nt < 16; nt++) {
                float2 b = *(const float2*)(bp + nt * 64);
                mma16n8k8(c2[nt], a0, a1, a2, a3, b.x, b.y);
            }
        }

        // ---- epilogue: pair-swap -> 4-col runs, fuse bias*rcut*h, red.v4 ----
        {
            const int row = g + (t & 1) * 8;           // this thread's edge row
            const int e   = e0 + m0 + row;
            const float rc = rcut[e];
            const int ji = idx_j[e];
            const int ii = idx_i[e];
            const float* hrow = g_h   + (size_t)ji * NB;
            float*       arow = g_agg + (size_t)ii * NB;
            const int cq = (t >> 1) * 4;               // 0 or 4 within n-tile
            const bool odd = (t & 1);

#pragma unroll
            for (int nt = 0; nt < 16; nt++) {
                // exchange: even t sends row g+8 pair (c.z,c.w), odd sends row g pair (c.x,c.y)
                float s0 = odd ? c2[nt].x : c2[nt].z;
                float s1 = odd ? c2[nt].y : c2[nt].w;
                float r0 = __shfl_xor_sync(0xffffffffu, s0, 1);
                float r1 = __shfl_xor_sync(0xffffffffu, s1, 1);
                float v0, v1, v2, v3;
                if (!odd) { v0 = c2[nt].x; v1 = c2[nt].y; v2 = r0; v3 = r1; }
                else      { v0 = r0; v1 = r1; v2 = c2[nt].z; v3 = c2[nt].w; }
                const int col = nt * 8 + cq;
                float4 hv = *(const float4*)(hrow + col);
                v0 = (v0 + b2s[col + 0]) * rc * hv.x;
                v1 = (v1 + b2s[col + 1]) * rc * hv.y;
                v2 = (v2 + b2s[col + 2]) * rc * hv.z;
                v3 = (v3 + b2s[col + 3]) * rc * hv.w;
                red_v4(arow + col, v0, v1, v2, v3);
            }
        }
        __syncthreads();   // protect fs before next tile's restage
    }
}

extern "C" void kernel_launch(void* const* d_in, const int* in_sizes, int n_in,
                              void* d_out, int out_size)
{
    const float* x       = (const float*)d_in[0];
    const float* f_ij    = (const float*)d_in[1];
    const float* rcut_ij = (const float*)d_in[2];
    const int*   idx_i   = (const int*)d_in[3];
    const int*   idx_j   = (const int*)d_in[4];
    const float* W_in2f  = (const float*)d_in[5];
    const float* W_filt1 = (const float*)d_in[6];
    const float* b_filt1 = (const float*)d_in[7];
    const float* W_filt2 = (const float*)d_in[8];
    const float* b_filt2 = (const float*)d_in[9];
    const float* W_out1  = (const float*)d_in[10];
    const float* b_out1  = (const float*)d_in[11];
    const float* W_out2  = (const float*)d_in[12];
    const float* b_out2  = (const float*)d_in[13];
    float* out = (float*)d_out;

    void *p_h = nullptr, *p_agg = nullptr, *p_t = nullptr;
    cudaGetSymbolAddress(&p_h, g_h);
    cudaGetSymbolAddress(&p_agg, g_agg);
    cudaGetSymbolAddress(&p_t, g_t);
    float* h   = (float*)p_h;
    float* agg = (float*)p_agg;
    float* t   = (float*)p_t;

    int nsm = 148;
    cudaDeviceGetAttribute(&nsm, cudaDevAttrMultiProcessorCount, 0);

    static int configured = 0;
    if (!configured) {
        cudaFuncSetAttribute(edge_kernel,
                             cudaFuncAttributeMaxDynamicSharedMemorySize, SMEM_BYTES);
        configured = 1;
    }

    // 1) zero accumulator
    {
        int n4 = (N_ATOMS * NB) / 4;
        zero_kernel<<<(n4 + 255) / 256, 256>>>((float4*)agg, n4);
    }
    // 2) h = x @ W_in2f
    gemm128_kernel<false, false><<<(N_ATOMS + 15) / 16, 128>>>(x, W_in2f, nullptr, h, N_ATOMS);
    // 3) fused mma edge kernel
    edge_kernel<<<nsm, ET, SMEM_BYTES>>>(f_ij, rcut_ij, idx_i, idx_j,
                                         W_filt1, b_filt1, W_filt2, b_filt2);
    // 4) t = ssp(agg @ W_out1 + b_out1)
    gemm128_kernel<true, true><<<(N_ATOMS + 15) / 16, 128>>>(agg, W_out1, b_out1, t, N_ATOMS);
    // 5) out = t @ W_out2 + b_out2
    gemm128_kernel<false, true><<<(N_ATOMS + 15) / 16, 128>>>(t, W_out2, b_out2, out, N_ATOMS);
}

// round 6
// speedup vs baseline: 3.7959x; 1.8359x over previous
#include <cuda_runtime.h>
#include <cstdint>

// Problem constants
#define N_ATOMS 20000
#define N_EDGES 640000
#define NB      128
#define N_RBF   20

// -------- device scratch --------
__device__ float g_h[N_ATOMS * NB];
__device__ float g_agg[N_ATOMS * NB];

__device__ __forceinline__ uint32_t to_tf32_bits(float x) {
    uint32_t r; asm("cvt.rna.tf32.f32 %0, %1;" : "=r"(r) : "f"(x)); return r;
}
__device__ __forceinline__ float to_tf32(float x) {
    return __uint_as_float(to_tf32_bits(x));
}
#define LN2F 0.69314718055994531f
// exact softplus - ln2 (for the FFMA h-path feed? not needed there) and fast variant
__device__ __forceinline__ float ssp_fast(float x) {
    // softplus(x)-ln2 = max(x,0) + log(1+exp(-|x|)) - ln2 ; fast MUFU versions.
    return fmaxf(x, 0.0f) + __logf(1.0f + __expf(-fabsf(x))) - LN2F;
}

// m16n8k8 tf32 mma
__device__ __forceinline__ void mma16n8k8(float4& c,
                                          float a0, float a1, float a2, float a3,
                                          float b0, float b1) {
    asm volatile(
        "mma.sync.aligned.m16n8k8.row.col.f32.tf32.tf32.f32 "
        "{%0,%1,%2,%3}, {%4,%5,%6,%7}, {%8,%9}, {%0,%1,%2,%3};"
        : "+f"(c.x), "+f"(c.y), "+f"(c.z), "+f"(c.w)
        : "r"(__float_as_uint(a0)), "r"(__float_as_uint(a1)),
          "r"(__float_as_uint(a2)), "r"(__float_as_uint(a3)),
          "r"(__float_as_uint(b0)), "r"(__float_as_uint(b1)));
}

__device__ __forceinline__ void red_v4(float* p, float a, float b, float c, float d) {
    asm volatile("red.global.add.v4.f32 [%0], {%1, %2, %3, %4};"
                 :: "l"(p), "f"(a), "f"(b), "f"(c), "f"(d) : "memory");
}

// -------- zero kernel --------
__global__ void zero_kernel(float4* __restrict__ p, int n4) {
    int i = blockIdx.x * blockDim.x + threadIdx.x;
    if (i < n4) p[i] = make_float4(0.f, 0.f, 0.f, 0.f);
}

// -------- exact FFMA [rows,128]@[128,128] (h path), 8 rows/block --------
__global__ __launch_bounds__(128) void gemm128_kernel(
    const float* __restrict__ A, const float* __restrict__ W,
    float* __restrict__ C, int nrows)
{
    __shared__ float xs[8 * NB];
    const int row0 = blockIdx.x * 8;
    const int tid  = threadIdx.x;

    for (int i = tid; i < 8 * NB; i += 128) {
        int r = row0 + (i >> 7);
        xs[i] = (r < nrows) ? A[row0 * NB + i] : 0.0f;
    }
    __syncthreads();

    const int c = tid;
    float acc[8];
#pragma unroll
    for (int r = 0; r < 8; r++) acc[r] = 0.0f;

#pragma unroll 4
    for (int k = 0; k < NB; k++) {
        float w = W[k * NB + c];
#pragma unroll
        for (int r = 0; r < 8; r++) acc[r] += xs[r * NB + k] * w;
    }
#pragma unroll
    for (int r = 0; r < 8; r++) {
        int row = row0 + r;
        if (row < nrows) C[row * NB + c] = acc[r];
    }
}

// ======================= fused edge kernel (warp-decoupled) =======================
// 12 warps/CTA, each warp independently processes 16-edge groups:
//   layer1: c1 = f@W1 (mma tf32, K pad 20->24);  phi = tf32(ssp(c1+b1)) -> private smem
//   layer2: c2 = phi@W2 (mma tf32, K=128)
//   c2 pair-swapped into phi rows (in-place), then row-wise epilogue:
//   per edge: whole warp loads full h[idx_j] row, red.v4 full row into agg[idx_i].
#define EW 12
#define ET (EW * 32)
// smem float offsets
#define E_W1P 0           // 3*16*32*2  = 3072
#define E_W2P 3072        // 16*16*32*2 = 16384
#define E_B1  19456       // 128
#define E_B2  19584       // 128
#define E_FS  19712       // EW * 16*36  = 6912
#define E_PHI 26624       // EW * 16*132 = 25344
#define E_SMEMF 51968
#define E_SMEMB (E_SMEMF * 4)

__global__ __launch_bounds__(ET, 1) void edge_kernel(
    const float* __restrict__ f_ij, const float* __restrict__ rcut,
    const int* __restrict__ idx_i, const int* __restrict__ idx_j,
    const float* __restrict__ W1, const float* __restrict__ b1,
    const float* __restrict__ W2, const float* __restrict__ b2)
{
    extern __shared__ float sm[];
    const int tid  = threadIdx.x;
    const int warp = tid >> 5;
    const int lane = tid & 31;
    const int g    = lane >> 2;
    const int t    = lane & 3;

    // ---- stage W1 fragments (3 kt x 16 nt) ----
    for (int i = tid; i < 3 * 16 * 32; i += ET) {
        int kt = i >> 9, rem = i & 511, nt = rem >> 5, l = rem & 31;
        int gg = l >> 2, tt = l & 3;
        int k = kt * 8 + tt, n = nt * 8 + gg;
        float v0 = (k     < N_RBF) ? W1[k * NB + n]       : 0.0f;
        float v1 = (k + 4 < N_RBF) ? W1[(k + 4) * NB + n] : 0.0f;
        sm[E_W1P + i * 2 + 0] = to_tf32(v0);
        sm[E_W1P + i * 2 + 1] = to_tf32(v1);
    }
    // ---- stage W2 fragments (16 ks x 16 nt) ----
    for (int i = tid; i < 16 * 16 * 32; i += ET) {
        int ks = i >> 9, rem = i & 511, nt = rem >> 5, l = rem & 31;
        int gg = l >> 2, tt = l & 3;
        int k = ks * 8 + tt, n = nt * 8 + gg;
        sm[E_W2P + i * 2 + 0] = to_tf32(W2[k * NB + n]);
        sm[E_W2P + i * 2 + 1] = to_tf32(W2[(k + 4) * NB + n]);
    }
    for (int i = tid; i < NB; i += ET) {
        sm[E_B1 + i] = b1[i];
        sm[E_B2 + i] = b2[i];
    }
    __syncthreads();

    float* fsw = sm + E_FS  + warp * (16 * 36);
    float* phw = sm + E_PHI + warp * (16 * 132);

    // zero f padding cols 20..23 (only cols used beyond N_RBF)
    for (int i = lane; i < 16 * 4; i += 32) {
        int r = i >> 2, c = N_RBF + (i & 3);
        fsw[r * 36 + c] = 0.0f;
    }
    const float4 b2v = *(const float4*)(sm + E_B2 + lane * 4);

    const int ngroups = N_EDGES / 16;  // 40000

    for (int grp = blockIdx.x * EW + warp; grp < ngroups; grp += gridDim.x * EW) {
        const int e0 = grp * 16;

        // edge metadata: lanes 0..15 hold one edge each
        float rc_l = 0.0f; int ji_l = 0, ii_l = 0;
        if (lane < 16) {
            rc_l = __ldg(rcut + e0 + lane);
            ji_l = __ldg(idx_j + e0 + lane);
            ii_l = __ldg(idx_i + e0 + lane);
        }

        // ---- stage f (16 x 20, coalesced) ----
        {
            const float* fsrc = f_ij + (size_t)e0 * N_RBF;
#pragma unroll
            for (int it = 0; it < 10; it++) {
                int i = it * 32 + lane;     // < 320
                int r = i / N_RBF, c = i - r * N_RBF;
                fsw[r * 36 + c] = to_tf32(__ldg(fsrc + i));
            }
        }
        __syncwarp();

        // ---- layer 1 + ssp -> phi ----
        {
            float4 c1[16];
#pragma unroll
            for (int nt = 0; nt < 16; nt++) c1[nt] = make_float4(0.f, 0.f, 0.f, 0.f);
#pragma unroll
            for (int kt = 0; kt < 3; kt++) {
                const int kb = kt * 8;
                float a0 = fsw[g * 36 + kb + t];
                float a1 = fsw[(g + 8) * 36 + kb + t];
                float a2 = fsw[g * 36 + kb + t + 4];
                float a3 = fsw[(g + 8) * 36 + kb + t + 4];
                const float* bp = sm + E_W1P + ((kt * 16) * 32 + lane) * 2;
#pragma unroll
                for (int nt = 0; nt < 16; nt++) {
                    float2 b = *(const float2*)(bp + nt * 64);
                    mma16n8k8(c1[nt], a0, a1, a2, a3, b.x, b.y);
                }
            }
#pragma unroll
            for (int nt = 0; nt < 16; nt++) {
                const int n0 = nt * 8 + 2 * t;
                float bb0 = sm[E_B1 + n0], bb1 = sm[E_B1 + n0 + 1];
                float2 lo, hi;
                lo.x = to_tf32(ssp_fast(c1[nt].x + bb0));
                lo.y = to_tf32(ssp_fast(c1[nt].y + bb1));
                hi.x = to_tf32(ssp_fast(c1[nt].z + bb0));
                hi.y = to_tf32(ssp_fast(c1[nt].w + bb1));
                *(float2*)(phw + g * 132 + n0) = lo;
                *(float2*)(phw + (g + 8) * 132 + n0) = hi;
            }
        }
        __syncwarp();

        // ---- layer 2 ----
        float4 c2[16];
#pragma unroll
        for (int nt = 0; nt < 16; nt++) c2[nt] = make_float4(0.f, 0.f, 0.f, 0.f);
        for (int ks = 0; ks < 16; ks++) {
            const int kb = ks * 8;
            float a0 = phw[g * 132 + kb + t];
            float a1 = phw[(g + 8) * 132 + kb + t];
            float a2 = phw[g * 132 + kb + t + 4];
            float a3 = phw[(g + 8) * 132 + kb + t + 4];
            const float* bp = sm + E_W2P + ((ks * 16) * 32 + lane) * 2;
#pragma unroll
            for (int nt = 0; nt < 16; nt++) {
                float2 b = *(const float2*)(bp + nt * 64);
                mma16n8k8(c2[nt], a0, a1, a2, a3, b.x, b.y);
            }
        }
        __syncwarp();   // all lanes done reading phi before overwrite

        // ---- pair-swap c2 into phi rows (in-place, warp-private) ----
        {
            const int cq  = (t >> 1) * 4;
            const bool odd = (t & 1);
            const int row = g + (odd ? 8 : 0);
#pragma unroll
            for (int nt = 0; nt < 16; nt++) {
                float s0 = odd ? c2[nt].x : c2[nt].z;
                float s1 = odd ? c2[nt].y : c2[nt].w;
                float r0 = __shfl_xor_sync(0xffffffffu, s0, 1);
                float r1 = __shfl_xor_sync(0xffffffffu, s1, 1);
                float4 v;
                if (!odd) { v.x = c2[nt].x; v.y = c2[nt].y; v.z = r0; v.w = r1; }
                else      { v.x = r0; v.y = r1; v.z = c2[nt].z; v.w = c2[nt].w; }
                *(float4*)(phw + row * 132 + nt * 8 + cq) = v;
            }
        }
        __syncwarp();

        // ---- row-wise epilogue: one full h/agg row per warp-instr ----
#pragma unroll 4
        for (int el = 0; el < 16; el++) {
            float rc = __shfl_sync(0xffffffffu, rc_l, el);
            int   ji = __shfl_sync(0xffffffffu, ji_l, el);
            int   ii = __shfl_sync(0xffffffffu, ii_l, el);
            float4 v  = *(const float4*)(phw + el * 132 + lane * 4);
            float4 hv = *(const float4*)(g_h + (size_t)ji * NB + lane * 4);
            red_v4(g_agg + (size_t)ii * NB + lane * 4,
                   (v.x + b2v.x) * rc * hv.x,
                   (v.y + b2v.y) * rc * hv.y,
                   (v.z + b2v.z) * rc * hv.z,
                   (v.w + b2v.w) * rc * hv.w);
        }
        __syncwarp();
    }
}

// ======================= fused out kernel (tf32 mma, warp-decoupled) =======================
// out = ssp(agg @ W_out1 + b_out1) @ W_out2 + b_out2, 16-atom groups per warp.
#define OW 8
#define OT (OW * 32)
#define O_W1P 0           // 16384
#define O_W2P 16384       // 16384
#define O_B1  32768
#define O_B2  32896
#define O_TILE 33024      // OW * 16*132 = 16896
#define O_SMEMF 49920
#define O_SMEMB (O_SMEMF * 4)

__global__ __launch_bounds__(OT, 1) void out_kernel(
    const float* __restrict__ A,     // g_agg
    const float* __restrict__ W1, const float* __restrict__ b1,
    const float* __restrict__ W2, const float* __restrict__ b2,
    float* __restrict__ out)
{
    extern __shared__ float sm[];
    const int tid  = threadIdx.x;
    const int warp = tid >> 5;
    const int lane = tid & 31;
    const int g    = lane >> 2;
    const int t    = lane & 3;

    // stage both weight fragment sets (16 ks x 16 nt each)
    for (int i = tid; i < 16 * 16 * 32; i += OT) {
        int ks = i >> 9, rem = i & 511, nt = rem >> 5, l = rem & 31;
        int gg = l >> 2, tt = l & 3;
        int k = ks * 8 + tt, n = nt * 8 + gg;
        sm[O_W1P + i * 2 + 0] = to_tf32(W1[k * NB + n]);
        sm[O_W1P + i * 2 + 1] = to_tf32(W1[(k + 4) * NB + n]);
        sm[O_W2P + i * 2 + 0] = to_tf32(W2[k * NB + n]);
        sm[O_W2P + i * 2 + 1] = to_tf32(W2[(k + 4) * NB + n]);
    }
    for (int i = tid; i < NB; i += OT) {
        sm[O_B1 + i] = b1[i];
        sm[O_B2 + i] = b2[i];
    }
    __syncthreads();

    float* tw = sm + O_TILE + warp * (16 * 132);
    const float4 b2v = *(const float4*)(sm + O_B2 + lane * 4);
    const int cq  = (t >> 1) * 4;
    const bool odd = (t & 1);
    const int srow = g + (odd ? 8 : 0);

    const int ngroups = N_ATOMS / 16;   // 1250 exact

    for (int grp = blockIdx.x * OW + warp; grp < ngroups; grp += gridDim.x * OW) {
        const int r0 = grp * 16;

        // stage A rows (tf32-rounded)
#pragma unroll 4
        for (int el = 0; el < 16; el++) {
            float4 v = *(const float4*)(A + (size_t)(r0 + el) * NB + lane * 4);
            v.x = to_tf32(v.x); v.y = to_tf32(v.y);
            v.z = to_tf32(v.z); v.w = to_tf32(v.w);
            *(float4*)(tw + el * 132 + lane * 4) = v;
        }
        __syncwarp();

        // layer 1
        {
            float4 c1[16];
#pragma unroll
            for (int nt = 0; nt < 16; nt++) c1[nt] = make_float4(0.f, 0.f, 0.f, 0.f);
            for (int ks = 0; ks < 16; ks++) {
                const int kb = ks * 8;
                float a0 = tw[g * 132 + kb + t];
                float a1 = tw[(g + 8) * 132 + kb + t];
                float a2 = tw[g * 132 + kb + t + 4];
                float a3 = tw[(g + 8) * 132 + kb + t + 4];
                const float* bp = sm + O_W1P + ((ks * 16) * 32 + lane) * 2;
#pragma unroll
                for (int nt = 0; nt < 16; nt++) {
                    float2 b = *(const float2*)(bp + nt * 64);
                    mma16n8k8(c1[nt], a0, a1, a2, a3, b.x, b.y);
                }
            }
            __syncwarp();   // done reading A before overwrite
            // ssp + b1, pair-swap into tile (in-place)
#pragma unroll
            for (int nt = 0; nt < 16; nt++) {
                const int n0 = nt * 8 + 2 * t;
                float bb0 = sm[O_B1 + n0], bb1 = sm[O_B1 + n0 + 1];
                float sx = to_tf32(ssp_fast(c1[nt].x + bb0));
                float sy = to_tf32(ssp_fast(c1[nt].y + bb1));
                float sz = to_tf32(ssp_fast(c1[nt].z + bb0));
                float sw_ = to_tf32(ssp_fast(c1[nt].w + bb1));
                float s0 = odd ? sx : sz;
                float s1 = odd ? sy : sw_;
                float r0s = __shfl_xor_sync(0xffffffffu, s0, 1);
                float r1s = __shfl_xor_sync(0xffffffffu, s1, 1);
                float4 v;
                if (!odd) { v.x = sx;  v.y = sy;  v.z = r0s; v.w = r1s; }
                else      { v.x = r0s; v.y = r1s; v.z = sz;  v.w = sw_; }
                *(float4*)(tw + srow * 132 + nt * 8 + cq) = v;
            }
        }
        __syncwarp();

        // layer 2
        float4 c2[16];
#pragma unroll
        for (int nt = 0; nt < 16; nt++) c2[nt] = make_float4(0.f, 0.f, 0.f, 0.f);
        for (int ks = 0; ks < 16; ks++) {
            const int kb = ks * 8;
            float a0 = tw[g * 132 + kb + t];
            float a1 = tw[(g + 8) * 132 + kb + t];
            float a2 = tw[g * 132 + kb + t + 4];
            float a3 = tw[(g + 8) * 132 + kb + t + 4];
            const float* bp = sm + O_W2P + ((ks * 16) * 32 + lane) * 2;
#pragma unroll
            for (int nt = 0; nt < 16; nt++) {
                float2 b = *(const float2*)(bp + nt * 64);
                mma16n8k8(c2[nt], a0, a1, a2, a3, b.x, b.y);
            }
        }
        __syncwarp();

        // pair-swap c2 into tile (raw; bias applied at store)
#pragma unroll
        for (int nt = 0; nt < 16; nt++) {
            float s0 = odd ? c2[nt].x : c2[nt].z;
            float s1 = odd ? c2[nt].y : c2[nt].w;
            float r0s = __shfl_xor_sync(0xffffffffu, s0, 1);
            float r1s = __shfl_xor_sync(0xffffffffu, s1, 1);
            float4 v;
            if (!odd) { v.x = c2[nt].x; v.y = c2[nt].y; v.z = r0s; v.w = r1s; }
            else      { v.x = r0s; v.y = r1s; v.z = c2[nt].z; v.w = c2[nt].w; }
            *(float4*)(tw + srow * 132 + nt * 8 + cq) = v;
        }
        __syncwarp();

        // coalesced store: one full output row per warp-instr
#pragma unroll 4
        for (int el = 0; el < 16; el++) {
            float4 v = *(const float4*)(tw + el * 132 + lane * 4);
            v.x += b2v.x; v.y += b2v.y; v.z += b2v.z; v.w += b2v.w;
            *(float4*)(out + (size_t)(r0 + el) * NB + lane * 4) = v;
        }
        __syncwarp();
    }
}

extern "C" void kernel_launch(void* const* d_in, const int* in_sizes, int n_in,
                              void* d_out, int out_size)
{
    const float* x       = (const float*)d_in[0];
    const float* f_ij    = (const float*)d_in[1];
    const float* rcut_ij = (const float*)d_in[2];
    const int*   idx_i   = (const int*)d_in[3];
    const int*   idx_j   = (const int*)d_in[4];
    const float* W_in2f  = (const float*)d_in[5];
    const float* W_filt1 = (const float*)d_in[6];
    const float* b_filt1 = (const float*)d_in[7];
    const float* W_filt2 = (const float*)d_in[8];
    const float* b_filt2 = (const float*)d_in[9];
    const float* W_out1  = (const float*)d_in[10];
    const float* b_out1  = (const float*)d_in[11];
    const float* W_out2  = (const float*)d_in[12];
    const float* b_out2  = (const float*)d_in[13];
    float* out = (float*)d_out;

    void *p_h = nullptr, *p_agg = nullptr;
    cudaGetSymbolAddress(&p_h, g_h);
    cudaGetSymbolAddress(&p_agg, g_agg);
    float* h   = (float*)p_h;
    float* agg = (float*)p_agg;

    int nsm = 148;
    cudaDeviceGetAttribute(&nsm, cudaDevAttrMultiProcessorCount, 0);

    static int configured = 0;
    if (!configured) {
        cudaFuncSetAttribute(edge_kernel,
                             cudaFuncAttributeMaxDynamicSharedMemorySize, E_SMEMB);
        cudaFuncSetAttribute(out_kernel,
                             cudaFuncAttributeMaxDynamicSharedMemorySize, O_SMEMB);
        configured = 1;
    }

    // 1) zero accumulator
    {
        int n4 = (N_ATOMS * NB) / 4;
        zero_kernel<<<(n4 + 255) / 256, 256>>>((float4*)agg, n4);
    }
    // 2) h = x @ W_in2f (exact FFMA)
    gemm128_kernel<<<(N_ATOMS + 7) / 8, 128>>>(x, W_in2f, h, N_ATOMS);
    // 3) fused edge kernel
    edge_kernel<<<nsm, ET, E_SMEMB>>>(f_ij, rcut_ij, idx_i, idx_j,
                                      W_filt1, b_filt1, W_filt2, b_filt2);
    // 4+5) fused output MLP
    out_kernel<<<nsm, OT, O_SMEMB>>>(agg, W_out1, b_out1, W_out2, b_out2, out);
}